// round 2
// baseline (speedup 1.0000x reference)
#include <cuda_runtime.h>
#include <cuda_bf16.h>

// Problem constants
#define BDIM  2
#define NNODE 4096
#define FIN   256
#define NH    8
#define HD    32
#define HDIM  256          // NH*HD
#define GSLOPE 0.2f

// Attention tiling
#define TI 16              // i rows per CTA
#define JT 32              // j chunk
#define SWPAD 18           // padded inner dim of w tile (even -> 8B aligned, 2-way bank conflict only)

// Scratch (device globals: no allocation allowed)
__device__ float g_Wh[(size_t)BDIM*NNODE*HDIM];   // 8 MB
__device__ float g_s1[(size_t)BDIM*NNODE*NH];
__device__ float g_s2[(size_t)BDIM*NNODE*NH];

// ---------------------------------------------------------------------------
// packed fp32x2 FMA (sm_100a): d.lo += a.lo*b.lo ; d.hi += a.hi*b.hi
__device__ __forceinline__ void ffma2(unsigned long long& d, unsigned long long a, unsigned long long b) {
    asm("fma.rn.f32x2 %0, %1, %2, %3;" : "=l"(d) : "l"(a), "l"(b), "l"(d));
}
__device__ __forceinline__ unsigned long long pack2(float x) {
    unsigned long long r;
    asm("mov.b64 %0, {%1, %2};" : "=l"(r) : "f"(x), "f"(x));
    return r;
}

// ---------------------------------------------------------------------------
// Kernel 1: Wh = h @ W    (M=8192, K=256, N=256), fp32 tiled
__global__ __launch_bounds__(256) void gemm_kernel(const float* __restrict__ A,
                                                   const float* __restrict__ Bm) {
    __shared__ float As[16][64];
    __shared__ float Bs[16][64];
    int t = threadIdx.x;
    int tx = t & 15, ty = t >> 4;
    int row0 = blockIdx.y * 64;
    int col0 = blockIdx.x * 64;
    float acc[4][4] = {};
    int idx = t * 4;
    for (int k0 = 0; k0 < FIN; k0 += 16) {
        {   // A tile 64x16, store transposed
            int m = idx >> 4;
            int k = idx & 15;
            float4 v = *reinterpret_cast<const float4*>(&A[(size_t)(row0 + m) * FIN + k0 + k]);
            As[k + 0][m] = v.x; As[k + 1][m] = v.y; As[k + 2][m] = v.z; As[k + 3][m] = v.w;
        }
        {   // B tile 16x64
            int k = idx >> 6;
            int n = idx & 63;
            *reinterpret_cast<float4*>(&Bs[k][n]) =
                *reinterpret_cast<const float4*>(&Bm[(size_t)(k0 + k) * HDIM + col0 + n]);
        }
        __syncthreads();
#pragma unroll
        for (int k = 0; k < 16; k++) {
            float4 a4 = *reinterpret_cast<const float4*>(&As[k][ty * 4]);
            float4 b4 = *reinterpret_cast<const float4*>(&Bs[k][tx * 4]);
            float av[4] = {a4.x, a4.y, a4.z, a4.w};
            float bv[4] = {b4.x, b4.y, b4.z, b4.w};
#pragma unroll
            for (int i = 0; i < 4; i++)
#pragma unroll
                for (int j = 0; j < 4; j++) acc[i][j] += av[i] * bv[j];
        }
        __syncthreads();
    }
#pragma unroll
    for (int i = 0; i < 4; i++) {
        float4 v = make_float4(acc[i][0], acc[i][1], acc[i][2], acc[i][3]);
        *reinterpret_cast<float4*>(&g_Wh[(size_t)(row0 + ty * 4 + i) * HDIM + col0 + tx * 4]) = v;
    }
}

// ---------------------------------------------------------------------------
// Kernel 2: s1[bn,h] = <Wh[bn, h*32: ], a[h, :32]> ; s2 uses a[h, 32:64]
__global__ __launch_bounds__(256) void s_kernel(const float* __restrict__ a) {
    int gw = (blockIdx.x * blockDim.x + threadIdx.x) >> 5;   // row 0..8191
    int lane = threadIdx.x & 31;
    if (gw >= BDIM * NNODE) return;
    const float* row = g_Wh + (size_t)gw * HDIM;
#pragma unroll
    for (int h = 0; h < NH; h++) {
        float v  = row[h * HD + lane];
        float p1 = v * a[h * (2 * HD) + lane];
        float p2 = v * a[h * (2 * HD) + HD + lane];
#pragma unroll
        for (int off = 16; off; off >>= 1) {
            p1 += __shfl_xor_sync(0xffffffffu, p1, off);
            p2 += __shfl_xor_sync(0xffffffffu, p2, off);
        }
        if (lane == 0) {
            g_s1[gw * NH + h] = p1;
            g_s2[gw * NH + h] = p2;
        }
    }
}

// ---------------------------------------------------------------------------
// Kernel 3: fused masked-softmax attention + PV + ELU.
// Grid: BDIM * (NNODE/TI) blocks, 256 threads.
// No max-subtraction needed (logits bounded; see analysis).
#define SM_WH   0                              // JT*HDIM        = 8192 floats
#define SM_W    (SM_WH + JT*HDIM)              // NH*JT*SWPAD    = 4608
#define SM_SI   (SM_W + NH*JT*SWPAD)           // TI*NH          = 128
#define SM_SJ   (SM_SI + TI*NH)                // NH*JT          = 256 (transposed [h][jj])
#define SM_DEN  (SM_SJ + NH*JT)                // TI*NH          = 128
#define SM_FLOATS (SM_DEN + TI*NH)             // 13312 floats = 53248 bytes

__global__ __launch_bounds__(256) void attn_kernel(const int* __restrict__ adj,
                                                   float* __restrict__ out) {
    extern __shared__ float sm[];
    float* sWh  = sm + SM_WH;
    float* sw   = sm + SM_W;
    float* sis  = sm + SM_SI;
    float* sjs  = sm + SM_SJ;
    float* sden = sm + SM_DEN;

    const int t    = threadIdx.x;
    const int b    = blockIdx.x >> 8;            // NNODE/TI = 256 tiles per batch
    const int i0   = (blockIdx.x & 255) * TI;
    const int lane = t & 31;

    // phase A mapping
    const int jj = t & 31;
    const int ib = t >> 5;                       // warp id = i base
    // phase B mapping
    const int h = t >> 5;
    const int d = t & 31;

    union { unsigned long long u[TI / 2]; float f[TI]; } acc;
#pragma unroll
    for (int p = 0; p < TI / 2; p++) acc.u[p] = 0ull;
    float dp[2][NH];
#pragma unroll
    for (int q = 0; q < 2; q++)
#pragma unroll
        for (int hh = 0; hh < NH; hh++) dp[q][hh] = 0.f;

    if (t < TI * NH)
        sis[t] = g_s1[(size_t)(b * NNODE + i0 + (t >> 3)) * NH + (t & 7)];

    const size_t adj_base = ((size_t)b * NNODE + i0) * NNODE;
    const float4* Wh4b = reinterpret_cast<const float4*>(g_Wh + (size_t)b * NNODE * HDIM);

    for (int j0 = 0; j0 < NNODE; j0 += JT) {
        // ---- stage Wh[j0:j0+JT, :] and s_j chunk
        {
            const float4* src = Wh4b + (size_t)j0 * (HDIM / 4);
            float4* dst = reinterpret_cast<float4*>(sWh);
#pragma unroll
            for (int r = 0; r < (JT * HDIM / 4) / 256; r++)
                dst[t + r * 256] = src[t + r * 256];
            // s_j transposed: sjs[h*JT + j]
            int jv = t >> 3, hh = t & 7;
            sjs[hh * JT + jv] = g_s2[(size_t)(b * NNODE + j0 + jv) * NH + hh];
        }
        __syncthreads();

        // ---- phase A: weights w = adj * exp(lrelu(s_i + s_j)) for all (i,h,jj)
#pragma unroll
        for (int q = 0; q < 2; q++) {
            int ii = ib + q * 8;
            int adjv = adj[adj_base + (size_t)ii * NNODE + j0 + jj];
#pragma unroll
            for (int hh = 0; hh < NH; hh++) {
                float e = sis[ii * NH + hh] + sjs[hh * JT + jj];
                e = fmaxf(e, GSLOPE * e);
                float ex = __expf(e);
                float w = adjv ? ex : 0.0f;
                sw[(hh * JT + jj) * SWPAD + ii] = w;
                dp[q][hh] += w;
            }
        }
        __syncthreads();

        // ---- phase B: acc[i] += w[i,h,jj] * Wh[jj, h*32+d]  (packed f32x2)
#pragma unroll 4
        for (int j = 0; j < JT; j++) {
            float whv = sWh[j * HDIM + (h << 5) + d];
            unsigned long long whv2 = pack2(whv);
            const unsigned long long* wp =
                reinterpret_cast<const unsigned long long*>(&sw[(h * JT + j) * SWPAD]);
#pragma unroll
            for (int p = 0; p < TI / 2; p++) ffma2(acc.u[p], wp[p], whv2);
        }
        __syncthreads();
    }

    // ---- denominators: warp-reduce dp over lanes (lanes = jj slices)
#pragma unroll
    for (int q = 0; q < 2; q++)
#pragma unroll
        for (int hh = 0; hh < NH; hh++) {
            float v = dp[q][hh];
#pragma unroll
            for (int off = 16; off; off >>= 1) v += __shfl_xor_sync(0xffffffffu, v, off);
            if (lane == 0) sden[(ib + q * 8) * NH + hh] = v;
        }
    __syncthreads();

    // ---- epilogue: divide + ELU, coalesced store
#pragma unroll
    for (int i = 0; i < TI; i++) {
        float x = acc.f[i] / sden[i * NH + h];
        x = x > 0.f ? x : expm1f(x);
        out[(size_t)(b * NNODE + i0 + i) * HDIM + t] = x;
    }
}

// ---------------------------------------------------------------------------
extern "C" void kernel_launch(void* const* d_in, const int* in_sizes, int n_in,
                              void* d_out, int out_size) {
    const float* h   = (const float*)d_in[0];
    const int*   adj = (const int*)d_in[1];
    const float* W   = (const float*)d_in[2];
    const float* a   = (const float*)d_in[3];
    float* out = (float*)d_out;

    // 1) Wh = h @ W
    gemm_kernel<<<dim3(HDIM / 64, (BDIM * NNODE) / 64), 256>>>(h, W);
    // 2) attention logit projections
    s_kernel<<<(BDIM * NNODE * 32) / 256, 256>>>(a);
    // 3) fused attention
    cudaFuncSetAttribute(attn_kernel, cudaFuncAttributeMaxDynamicSharedMemorySize,
                         SM_FLOATS * sizeof(float));
    attn_kernel<<<BDIM * (NNODE / TI), 256, SM_FLOATS * sizeof(float)>>>(adj, out);
}

// round 3
// speedup vs baseline: 1.0019x; 1.0019x over previous
#include <cuda_runtime.h>
#include <cuda_bf16.h>

// Problem constants
#define BDIM  2
#define NNODE 4096
#define FIN   256
#define NH    8
#define HD    32
#define HDIM  256          // NH*HD
#define GSLOPE 0.2f

// Attention tiling
#define TI 16              // i rows per CTA
#define JT 32              // j chunk
#define SWPAD 18           // padded inner dim of w tile (even -> 8B aligned, 2-way bank conflict only)

// Scratch (device globals: no allocation allowed)
__device__ float g_Wh[(size_t)BDIM*NNODE*HDIM];   // 8 MB
__device__ float g_s1[(size_t)BDIM*NNODE*NH];
__device__ float g_s2[(size_t)BDIM*NNODE*NH];

// ---------------------------------------------------------------------------
// packed fp32x2 FMA (sm_100a): d.lo += a.lo*b.lo ; d.hi += a.hi*b.hi
__device__ __forceinline__ void ffma2(unsigned long long& d, unsigned long long a, unsigned long long b) {
    asm("fma.rn.f32x2 %0, %1, %2, %3;" : "=l"(d) : "l"(a), "l"(b), "l"(d));
}
__device__ __forceinline__ unsigned long long pack2(float x) {
    unsigned long long r;
    asm("mov.b64 %0, {%1, %2};" : "=l"(r) : "f"(x), "f"(x));
    return r;
}

// ---------------------------------------------------------------------------
// Kernel 1: Wh = h @ W    (M=8192, K=256, N=256), fp32 tiled
__global__ __launch_bounds__(256) void gemm_kernel(const float* __restrict__ A,
                                                   const float* __restrict__ Bm) {
    __shared__ float As[16][64];
    __shared__ float Bs[16][64];
    int t = threadIdx.x;
    int tx = t & 15, ty = t >> 4;
    int row0 = blockIdx.y * 64;
    int col0 = blockIdx.x * 64;
    float acc[4][4] = {};
    int idx = t * 4;
    for (int k0 = 0; k0 < FIN; k0 += 16) {
        {   // A tile 64x16, store transposed
            int m = idx >> 4;
            int k = idx & 15;
            float4 v = *reinterpret_cast<const float4*>(&A[(size_t)(row0 + m) * FIN + k0 + k]);
            As[k + 0][m] = v.x; As[k + 1][m] = v.y; As[k + 2][m] = v.z; As[k + 3][m] = v.w;
        }
        {   // B tile 16x64
            int k = idx >> 6;
            int n = idx & 63;
            *reinterpret_cast<float4*>(&Bs[k][n]) =
                *reinterpret_cast<const float4*>(&Bm[(size_t)(k0 + k) * HDIM + col0 + n]);
        }
        __syncthreads();
#pragma unroll
        for (int k = 0; k < 16; k++) {
            float4 a4 = *reinterpret_cast<const float4*>(&As[k][ty * 4]);
            float4 b4 = *reinterpret_cast<const float4*>(&Bs[k][tx * 4]);
            float av[4] = {a4.x, a4.y, a4.z, a4.w};
            float bv[4] = {b4.x, b4.y, b4.z, b4.w};
#pragma unroll
            for (int i = 0; i < 4; i++)
#pragma unroll
                for (int j = 0; j < 4; j++) acc[i][j] += av[i] * bv[j];
        }
        __syncthreads();
    }
#pragma unroll
    for (int i = 0; i < 4; i++) {
        float4 v = make_float4(acc[i][0], acc[i][1], acc[i][2], acc[i][3]);
        *reinterpret_cast<float4*>(&g_Wh[(size_t)(row0 + ty * 4 + i) * HDIM + col0 + tx * 4]) = v;
    }
}

// ---------------------------------------------------------------------------
// Kernel 2: s1[bn,h] = <Wh[bn, h*32: ], a[h, :32]> ; s2 uses a[h, 32:64]
__global__ __launch_bounds__(256) void s_kernel(const float* __restrict__ a) {
    int gw = (blockIdx.x * blockDim.x + threadIdx.x) >> 5;   // row 0..8191
    int lane = threadIdx.x & 31;
    if (gw >= BDIM * NNODE) return;
    const float* row = g_Wh + (size_t)gw * HDIM;
#pragma unroll
    for (int h = 0; h < NH; h++) {
        float v  = row[h * HD + lane];
        float p1 = v * a[h * (2 * HD) + lane];
        float p2 = v * a[h * (2 * HD) + HD + lane];
#pragma unroll
        for (int off = 16; off; off >>= 1) {
            p1 += __shfl_xor_sync(0xffffffffu, p1, off);
            p2 += __shfl_xor_sync(0xffffffffu, p2, off);
        }
        if (lane == 0) {
            g_s1[gw * NH + h] = p1;
            g_s2[gw * NH + h] = p2;
        }
    }
}

// ---------------------------------------------------------------------------
// Kernel 3: fused masked-softmax attention + PV + ELU.
// Grid: BDIM * (NNODE/TI) blocks, 256 threads.
// No max-subtraction needed (logits bounded; see analysis).
#define SM_WH   0                              // JT*HDIM        = 8192 floats
#define SM_W    (SM_WH + JT*HDIM)              // NH*JT*SWPAD    = 4608
#define SM_SI   (SM_W + NH*JT*SWPAD)           // TI*NH          = 128
#define SM_SJ   (SM_SI + TI*NH)                // NH*JT          = 256 (transposed [h][jj])
#define SM_DEN  (SM_SJ + NH*JT)                // TI*NH          = 128
#define SM_FLOATS (SM_DEN + TI*NH)             // 13312 floats = 53248 bytes

__global__ __launch_bounds__(256) void attn_kernel(const int* __restrict__ adj,
                                                   float* __restrict__ out) {
    extern __shared__ float sm[];
    float* sWh  = sm + SM_WH;
    float* sw   = sm + SM_W;
    float* sis  = sm + SM_SI;
    float* sjs  = sm + SM_SJ;
    float* sden = sm + SM_DEN;

    const int t    = threadIdx.x;
    const int b    = blockIdx.x >> 8;            // NNODE/TI = 256 tiles per batch
    const int i0   = (blockIdx.x & 255) * TI;
    const int lane = t & 31;

    // phase A mapping
    const int jj = t & 31;
    const int ib = t >> 5;                       // warp id = i base
    // phase B mapping
    const int h = t >> 5;
    const int d = t & 31;

    union { unsigned long long u[TI / 2]; float f[TI]; } acc;
#pragma unroll
    for (int p = 0; p < TI / 2; p++) acc.u[p] = 0ull;
    float dp[2][NH];
#pragma unroll
    for (int q = 0; q < 2; q++)
#pragma unroll
        for (int hh = 0; hh < NH; hh++) dp[q][hh] = 0.f;

    if (t < TI * NH)
        sis[t] = g_s1[(size_t)(b * NNODE + i0 + (t >> 3)) * NH + (t & 7)];

    const size_t adj_base = ((size_t)b * NNODE + i0) * NNODE;
    const float4* Wh4b = reinterpret_cast<const float4*>(g_Wh + (size_t)b * NNODE * HDIM);

    for (int j0 = 0; j0 < NNODE; j0 += JT) {
        // ---- stage Wh[j0:j0+JT, :] and s_j chunk
        {
            const float4* src = Wh4b + (size_t)j0 * (HDIM / 4);
            float4* dst = reinterpret_cast<float4*>(sWh);
#pragma unroll
            for (int r = 0; r < (JT * HDIM / 4) / 256; r++)
                dst[t + r * 256] = src[t + r * 256];
            // s_j transposed: sjs[h*JT + j]
            int jv = t >> 3, hh = t & 7;
            sjs[hh * JT + jv] = g_s2[(size_t)(b * NNODE + j0 + jv) * NH + hh];
        }
        __syncthreads();

        // ---- phase A: weights w = adj * exp(lrelu(s_i + s_j)) for all (i,h,jj)
#pragma unroll
        for (int q = 0; q < 2; q++) {
            int ii = ib + q * 8;
            int adjv = adj[adj_base + (size_t)ii * NNODE + j0 + jj];
#pragma unroll
            for (int hh = 0; hh < NH; hh++) {
                float e = sis[ii * NH + hh] + sjs[hh * JT + jj];
                e = fmaxf(e, GSLOPE * e);
                float ex = __expf(e);
                float w = adjv ? ex : 0.0f;
                sw[(hh * JT + jj) * SWPAD + ii] = w;
                dp[q][hh] += w;
            }
        }
        __syncthreads();

        // ---- phase B: acc[i] += w[i,h,jj] * Wh[jj, h*32+d]  (packed f32x2)
#pragma unroll 4
        for (int j = 0; j < JT; j++) {
            float whv = sWh[j * HDIM + (h << 5) + d];
            unsigned long long whv2 = pack2(whv);
            const unsigned long long* wp =
                reinterpret_cast<const unsigned long long*>(&sw[(h * JT + j) * SWPAD]);
#pragma unroll
            for (int p = 0; p < TI / 2; p++) ffma2(acc.u[p], wp[p], whv2);
        }
        __syncthreads();
    }

    // ---- denominators: warp-reduce dp over lanes (lanes = jj slices)
#pragma unroll
    for (int q = 0; q < 2; q++)
#pragma unroll
        for (int hh = 0; hh < NH; hh++) {
            float v = dp[q][hh];
#pragma unroll
            for (int off = 16; off; off >>= 1) v += __shfl_xor_sync(0xffffffffu, v, off);
            if (lane == 0) sden[(ib + q * 8) * NH + hh] = v;
        }
    __syncthreads();

    // ---- epilogue: divide + ELU, coalesced store
#pragma unroll
    for (int i = 0; i < TI; i++) {
        float x = acc.f[i] / sden[i * NH + h];
        x = x > 0.f ? x : expm1f(x);
        out[(size_t)(b * NNODE + i0 + i) * HDIM + t] = x;
    }
}

// ---------------------------------------------------------------------------
extern "C" void kernel_launch(void* const* d_in, const int* in_sizes, int n_in,
                              void* d_out, int out_size) {
    const float* h   = (const float*)d_in[0];
    const int*   adj = (const int*)d_in[1];
    const float* W   = (const float*)d_in[2];
    const float* a   = (const float*)d_in[3];
    float* out = (float*)d_out;

    // 1) Wh = h @ W
    gemm_kernel<<<dim3(HDIM / 64, (BDIM * NNODE) / 64), 256>>>(h, W);
    // 2) attention logit projections
    s_kernel<<<(BDIM * NNODE * 32) / 256, 256>>>(a);
    // 3) fused attention
    cudaFuncSetAttribute(attn_kernel, cudaFuncAttributeMaxDynamicSharedMemorySize,
                         SM_FLOATS * sizeof(float));
    attn_kernel<<<BDIM * (NNODE / TI), 256, SM_FLOATS * sizeof(float)>>>(adj, out);
}

// round 7
// speedup vs baseline: 2.9819x; 2.9763x over previous
#include <cuda_runtime.h>
#include <cstdint>

#define BDIM  2
#define NNODE 4096
#define FIN   256
#define NH    8
#define HD    32
#define HDIM  256
#define GSLOPE 0.2f

#define TI 64                      // i rows per CTA
#define JT 32                      // j chunk
#define NCHUNK (NNODE / JT)        // 128

__device__ float    g_Wh[(size_t)BDIM * NNODE * HDIM];
__device__ float    g_s1[(size_t)BDIM * NNODE * NH];
__device__ float    g_s2[(size_t)BDIM * NNODE * NH];
__device__ uint32_t g_adjbits[(size_t)BDIM * 128 * NNODE];   // [b][jword][i]

// ---------------------------------------------------------------- helpers
// tf32 round-to-nearest; result is a b32 register whose bit pattern is valid fp32
__device__ __forceinline__ uint32_t rna_tf32(float x) {
    uint32_t r; asm("cvt.rna.tf32.f32 %0, %1;" : "=r"(r) : "f"(x)); return r;
}
__device__ __forceinline__ void mma_tf32(float* c,
                                         uint32_t a0, uint32_t a1, uint32_t a2, uint32_t a3,
                                         uint32_t b0, uint32_t b1) {
    asm volatile(
        "mma.sync.aligned.m16n8k8.row.col.f32.tf32.tf32.f32 "
        "{%0,%1,%2,%3}, {%4,%5,%6,%7}, {%8,%9}, {%0,%1,%2,%3};"
        : "+f"(c[0]), "+f"(c[1]), "+f"(c[2]), "+f"(c[3])
        : "r"(a0), "r"(a1), "r"(a2), "r"(a3), "r"(b0), "r"(b1));
}
// masked attention weight, tf32-rounded (bit pattern)
__device__ __forceinline__ uint32_t wfun(float sih, float sj, uint32_t bit) {
    float e = sih + sj;
    e = fmaxf(e, GSLOPE * e);
    uint32_t x = rna_tf32(__expf(e));
    return bit ? x : 0u;
}
__device__ __forceinline__ float elu(float x) { return x > 0.f ? x : expm1f(x); }

// ---------------------------------------------------------------- bits kernel
__global__ __launch_bounds__(256) void bits_kernel(const int* __restrict__ adj) {
    __shared__ uint32_t sm[8][128];
    int t = threadIdx.x, w = t >> 5, lane = t & 31;
    int rowbase = blockIdx.x * 8;
    const int* src = adj + (size_t)(rowbase + w) * NNODE;
#pragma unroll 4
    for (int wd = 0; wd < 128; wd++) {
        uint32_t m = __ballot_sync(0xffffffffu, src[wd * 32 + lane] != 0);
        if (lane == 0) sm[w][wd] = m;
    }
    __syncthreads();
    int bb = rowbase >> 12, ib = rowbase & 4095;
    for (int idx = t; idx < 1024; idx += 256) {
        int isub = idx & 7, wd = idx >> 3;
        g_adjbits[((size_t)(bb * 128 + wd)) * NNODE + ib + isub] = sm[isub][wd];
    }
}

// ---------------------------------------------------------------- gemm Wh=h@W
__global__ __launch_bounds__(256) void gemm_kernel(const float* __restrict__ A,
                                                   const float* __restrict__ Bm) {
    __shared__ float As[16][64];
    __shared__ float Bs[16][64];
    int t = threadIdx.x, tx = t & 15, ty = t >> 4;
    int row0 = blockIdx.y * 64, col0 = blockIdx.x * 64;
    float acc[4][4] = {};
    int idx = t * 4;
    for (int k0 = 0; k0 < FIN; k0 += 16) {
        {
            int m = idx >> 4, k = idx & 15;
            float4 v = *reinterpret_cast<const float4*>(&A[(size_t)(row0 + m) * FIN + k0 + k]);
            As[k + 0][m] = v.x; As[k + 1][m] = v.y; As[k + 2][m] = v.z; As[k + 3][m] = v.w;
        }
        {
            int k = idx >> 6, n = idx & 63;
            *reinterpret_cast<float4*>(&Bs[k][n]) =
                *reinterpret_cast<const float4*>(&Bm[(size_t)(k0 + k) * HDIM + col0 + n]);
        }
        __syncthreads();
#pragma unroll
        for (int k = 0; k < 16; k++) {
            float4 a4 = *reinterpret_cast<const float4*>(&As[k][ty * 4]);
            float4 b4 = *reinterpret_cast<const float4*>(&Bs[k][tx * 4]);
            float av[4] = {a4.x, a4.y, a4.z, a4.w};
            float bv[4] = {b4.x, b4.y, b4.z, b4.w};
#pragma unroll
            for (int i = 0; i < 4; i++)
#pragma unroll
                for (int j = 0; j < 4; j++) acc[i][j] += av[i] * bv[j];
        }
        __syncthreads();
    }
#pragma unroll
    for (int i = 0; i < 4; i++) {
        float4 v = make_float4(acc[i][0], acc[i][1], acc[i][2], acc[i][3]);
        *reinterpret_cast<float4*>(&g_Wh[(size_t)(row0 + ty * 4 + i) * HDIM + col0 + tx * 4]) = v;
    }
}

// ---------------------------------------------------------------- projections
__global__ __launch_bounds__(256) void s_kernel(const float* __restrict__ a) {
    int gw = (blockIdx.x * blockDim.x + threadIdx.x) >> 5;
    int lane = threadIdx.x & 31;
    if (gw >= BDIM * NNODE) return;
    const float* row = g_Wh + (size_t)gw * HDIM;
#pragma unroll
    for (int h = 0; h < NH; h++) {
        float v  = row[h * HD + lane];
        float p1 = v * a[h * (2 * HD) + lane];
        float p2 = v * a[h * (2 * HD) + HD + lane];
#pragma unroll
        for (int off = 16; off; off >>= 1) {
            p1 += __shfl_xor_sync(0xffffffffu, p1, off);
            p2 += __shfl_xor_sync(0xffffffffu, p2, off);
        }
        if (lane == 0) { g_s1[gw * NH + h] = p1; g_s2[gw * NH + h] = p2; }
    }
}

// ---------------------------------------------------------------- attn (mma.sync tf32)
// Grid: BDIM * (NNODE/TI) = 128 CTAs, 256 threads, warp w = head w, M=64 rows.
__global__ __launch_bounds__(256, 1) void attn_kernel(float* __restrict__ out) {
    __shared__ float    sWh[JT * HDIM];     // [k][d], plain layout, tf32-rounded
    __shared__ float    sjs[NH * JT];       // [h][j]
    __shared__ uint32_t smask[TI];          // adjacency word per row (current chunk)

    const int t = threadIdx.x;
    const int h = t >> 5;                   // warp = head
    const int lane = t & 31;
    const int quad = lane >> 2;             // 0..7
    const int qt = lane & 3;                // 0..3
    const int b = blockIdx.x >> 6;
    const int i0 = (blockIdx.x & 63) * TI;

    // per-thread row scores (rows r = 16m + 8q + quad, slot s = 2m+q)
    float si8[8];
#pragma unroll
    for (int s = 0; s < 8; s++) {
        int r = ((s >> 1) << 4) + ((s & 1) << 3) + quad;
        si8[s] = g_s1[((size_t)(b * NNODE + i0 + r)) * NH + h];
    }
    float dp[8];
#pragma unroll
    for (int s = 0; s < 8; s++) dp[s] = 0.f;
    float acc[4][4][4];
#pragma unroll
    for (int m = 0; m < 4; m++)
#pragma unroll
        for (int nt = 0; nt < 4; nt++)
#pragma unroll
            for (int q = 0; q < 4; q++) acc[m][nt][q] = 0.f;

    const float4* Wh4 = reinterpret_cast<const float4*>(g_Wh + (size_t)b * NNODE * HDIM);

    // prefetch regs
    float4 pWh[8];
    uint32_t pmask = 0;
    float psj;
    {
        const float4* src = Wh4;            // chunk 0: j0 = 0
#pragma unroll
        for (int r = 0; r < 8; r++) pWh[r] = src[t + r * 256];
        if (t < TI) pmask = g_adjbits[((size_t)(b * 128)) * NNODE + i0 + t];
        psj = g_s2[((size_t)(b * NNODE + (t >> 3))) * NH + (t & 7)];
    }

    for (int c = 0; c < NCHUNK; c++) {
        __syncthreads();                    // smem free (readers of prev chunk done)
        // stage (round Wh to tf32 so HW/denominator/numerator agree)
        {
            float4* dst = reinterpret_cast<float4*>(sWh);
#pragma unroll
            for (int r = 0; r < 8; r++) {
                float4 v = pWh[r];
                v.x = __uint_as_float(rna_tf32(v.x));
                v.y = __uint_as_float(rna_tf32(v.y));
                v.z = __uint_as_float(rna_tf32(v.z));
                v.w = __uint_as_float(rna_tf32(v.w));
                dst[t + r * 256] = v;
            }
            if (t < TI) smask[t] = pmask;
            sjs[(t & 7) * JT + (t >> 3)] = psj;
        }
        __syncthreads();

        // chunk-local constants
        uint32_t mrow[8];
#pragma unroll
        for (int s = 0; s < 8; s++) {
            int r = ((s >> 1) << 4) + ((s & 1) << 3) + quad;
            mrow[s] = smask[r];
        }
        float sj0[4], sj1[4];
#pragma unroll
        for (int kt = 0; kt < 4; kt++) {
            sj0[kt] = sjs[h * JT + 8 * kt + qt];
            sj1[kt] = sjs[h * JT + 8 * kt + qt + 4];
        }

        // prefetch next chunk (overlaps compute)
        if (c + 1 < NCHUNK) {
            const int j0 = (c + 1) * JT;
            const float4* src = Wh4 + (size_t)j0 * (HDIM / 4);
#pragma unroll
            for (int r = 0; r < 8; r++) pWh[r] = src[t + r * 256];
            if (t < TI) pmask = g_adjbits[((size_t)(b * 128 + (j0 >> 5))) * NNODE + i0 + t];
            psj = g_s2[((size_t)(b * NNODE + j0 + (t >> 3))) * NH + (t & 7)];
        }

        // compute: A fragments in-register, 4 k-tiles x 4 m-tiles x 4 n-tiles
#pragma unroll
        for (int kt = 0; kt < 4; kt++) {
            const int k0r = 8 * kt + qt;
            uint32_t bb[4][2];
#pragma unroll
            for (int nt = 0; nt < 4; nt++) {
                bb[nt][0] = __float_as_uint(sWh[k0r * HDIM + h * HD + 8 * nt + quad]);
                bb[nt][1] = __float_as_uint(sWh[(k0r + 4) * HDIM + h * HD + 8 * nt + quad]);
            }
            const float s0 = sj0[kt], s1 = sj1[kt];
#pragma unroll
            for (int m = 0; m < 4; m++) {
                uint32_t a0 = wfun(si8[2 * m],     s0, (mrow[2 * m]     >> k0r) & 1u);
                uint32_t a1 = wfun(si8[2 * m + 1], s0, (mrow[2 * m + 1] >> k0r) & 1u);
                uint32_t a2 = wfun(si8[2 * m],     s1, (mrow[2 * m]     >> (k0r + 4)) & 1u);
                uint32_t a3 = wfun(si8[2 * m + 1], s1, (mrow[2 * m + 1] >> (k0r + 4)) & 1u);
                dp[2 * m]     += __uint_as_float(a0) + __uint_as_float(a2);
                dp[2 * m + 1] += __uint_as_float(a1) + __uint_as_float(a3);
#pragma unroll
                for (int nt = 0; nt < 4; nt++)
                    mma_tf32(acc[m][nt], a0, a1, a2, a3, bb[nt][0], bb[nt][1]);
            }
        }
    }

    // denominators: sum over the 4 lanes of each quad (j partitioned by qt)
#pragma unroll
    for (int s = 0; s < 8; s++) {
        dp[s] += __shfl_xor_sync(0xffffffffu, dp[s], 1);
        dp[s] += __shfl_xor_sync(0xffffffffu, dp[s], 2);
    }

    // epilogue: divide + ELU + store
#pragma unroll
    for (int m = 0; m < 4; m++) {
        const float inv0 = 1.f / dp[2 * m];
        const float inv1 = 1.f / dp[2 * m + 1];
        const size_t row0 = (size_t)(b * NNODE + i0 + 16 * m + quad);
#pragma unroll
        for (int nt = 0; nt < 4; nt++) {
            const int col = h * HD + 8 * nt + 2 * qt;
            float2 v0 = make_float2(elu(acc[m][nt][0] * inv0), elu(acc[m][nt][1] * inv0));
            float2 v1 = make_float2(elu(acc[m][nt][2] * inv1), elu(acc[m][nt][3] * inv1));
            *reinterpret_cast<float2*>(out + row0 * HDIM + col) = v0;
            *reinterpret_cast<float2*>(out + (row0 + 8) * HDIM + col) = v1;
        }
    }
}

// ----------------------------------------------------------------------------
extern "C" void kernel_launch(void* const* d_in, const int* in_sizes, int n_in,
                              void* d_out, int out_size) {
    const float* h   = (const float*)d_in[0];
    const int*   adj = (const int*)d_in[1];
    const float* W   = (const float*)d_in[2];
    const float* a   = (const float*)d_in[3];
    float* out = (float*)d_out;

    gemm_kernel<<<dim3(HDIM / 64, (BDIM * NNODE) / 64), 256>>>(h, W);
    s_kernel<<<(BDIM * NNODE * 32) / 256, 256>>>(a);
    bits_kernel<<<(BDIM * NNODE) / 8, 256>>>(adj);
    attn_kernel<<<BDIM * (NNODE / TI), 256>>>(out);
}